// round 1
// baseline (speedup 1.0000x reference)
#include <cuda_runtime.h>
#include <math.h>

#define B_   16
#define C_   1536
#define N_   1024
#define M_   64
#define L_   128
#define G_   256
#define HID_ 512

// ---------------- scratch (device globals: no allocation allowed) ----------------
static __device__ float g_H   [B_ * 1024 * N_];   // 64 MB: rows 0..511 = h1 (cluster), 512..1023 = h2 (score)
static __device__ float g_F   [B_ * L_ * N_];     // f
static __device__ float g_P   [B_ * M_ * N_];     // scores p -> (in-place) transport P
static __device__ float g_T   [B_ * N_];          // T_i
static __device__ float g_RN  [B_ * N_];          // 1/max(||f_col||,1e-12)
static __device__ float g_D   [B_ * N_];          // discount
static __device__ float g_Ht  [B_ * HID_];
static __device__ float g_tok [B_ * G_];
static __device__ float g_aggp[B_ * 8 * L_ * M_]; // split-K partials for agg (deterministic)

// ---------------- big fused GEMM: h = relu(W * xf + b), 1024 output rows ----------------
// C[b,m,n] = relu(sum_k W(m,k) * x[b,k,n] + bias(m)); m<512 -> Wc1/bc1, else Ws1/bs1
__global__ __launch_bounds__(256, 2) void k_hidden(
    const float* __restrict__ x,
    const float* __restrict__ Wc1, const float* __restrict__ bc1,
    const float* __restrict__ Ws1, const float* __restrict__ bs1)
{
    const int b  = blockIdx.z;
    const int m0 = blockIdx.y * 128;
    const int n0 = blockIdx.x * 128;
    const float* W  = (m0 < HID_) ? (Wc1 + (size_t)m0 * C_) : (Ws1 + (size_t)(m0 - HID_) * C_);
    const float* bi = (m0 < HID_) ? (bc1 + m0) : (bs1 + (m0 - HID_));
    const float* X  = x + (size_t)b * C_ * N_;

    __shared__ float As[16][128];
    __shared__ float Bs[16][128];

    const int t  = threadIdx.x;
    const int tx = t & 15;
    const int ty = t >> 4;

    float acc[8][8];
#pragma unroll
    for (int i = 0; i < 8; i++)
#pragma unroll
        for (int j = 0; j < 8; j++) acc[i][j] = 0.f;

    for (int k0 = 0; k0 < C_; k0 += 16) {
#pragma unroll
        for (int p = 0; p < 2; p++) {
            int idx = t * 2 + p;            // 0..511 float4 units of A tile
            int row = idx >> 2;             // 0..127
            int c4  = idx & 3;              // 0..3
            float4 v = *reinterpret_cast<const float4*>(W + (size_t)row * C_ + k0 + c4 * 4);
            As[c4 * 4 + 0][row] = v.x; As[c4 * 4 + 1][row] = v.y;
            As[c4 * 4 + 2][row] = v.z; As[c4 * 4 + 3][row] = v.w;
        }
#pragma unroll
        for (int p = 0; p < 2; p++) {
            int idx = t * 2 + p;            // 0..511 float4 units of B tile
            int row = idx >> 5;             // 0..15
            int c4  = idx & 31;             // 0..31
            *reinterpret_cast<float4*>(&Bs[row][c4 * 4]) =
                *reinterpret_cast<const float4*>(X + (size_t)(k0 + row) * N_ + n0 + c4 * 4);
        }
        __syncthreads();
#pragma unroll
        for (int k = 0; k < 16; k++) {
            float a[8], bv[8];
            *reinterpret_cast<float4*>(&a[0])  = *reinterpret_cast<float4*>(&As[k][ty * 8]);
            *reinterpret_cast<float4*>(&a[4])  = *reinterpret_cast<float4*>(&As[k][ty * 8 + 4]);
            *reinterpret_cast<float4*>(&bv[0]) = *reinterpret_cast<float4*>(&Bs[k][tx * 8]);
            *reinterpret_cast<float4*>(&bv[4]) = *reinterpret_cast<float4*>(&Bs[k][tx * 8 + 4]);
#pragma unroll
            for (int i = 0; i < 8; i++)
#pragma unroll
                for (int j = 0; j < 8; j++) acc[i][j] = fmaf(a[i], bv[j], acc[i][j]);
        }
        __syncthreads();
    }

    float* O = g_H + (size_t)b * 1024 * N_;
#pragma unroll
    for (int i = 0; i < 8; i++) {
        const float bval = bi[ty * 8 + i];
        const int m = m0 + ty * 8 + i;
#pragma unroll
        for (int j = 0; j < 8; j++)
            O[(size_t)m * N_ + n0 + tx * 8 + j] = fmaxf(acc[i][j] + bval, 0.f);
    }
}

// ---------------- second-layer GEMMs: f (flag=0) / p (flag=1), K=512, no activation ----------------
__global__ __launch_bounds__(256) void k_gemm2(
    const float* __restrict__ A, const float* __restrict__ bias, int koff, int flag)
{
    const int b  = blockIdx.z;
    const int m0 = blockIdx.y * 64;
    const int n0 = blockIdx.x * 128;
    float* out = flag ? g_P : g_F;
    const int Mrows = flag ? M_ : L_;
    const float* Hsrc = g_H + (size_t)b * 1024 * N_ + (size_t)koff * N_;

    __shared__ float As[16][64];
    __shared__ float Bs[16][128];
    const int t = threadIdx.x, tx = t & 15, ty = t >> 4;

    float acc[4][8];
#pragma unroll
    for (int i = 0; i < 4; i++)
#pragma unroll
        for (int j = 0; j < 8; j++) acc[i][j] = 0.f;

    for (int k0 = 0; k0 < HID_; k0 += 16) {
        {
            int row = t >> 2, c4 = t & 3;   // 64 rows x 4 float4
            float4 v = *reinterpret_cast<const float4*>(A + (size_t)(m0 + row) * HID_ + k0 + c4 * 4);
            As[c4 * 4 + 0][row] = v.x; As[c4 * 4 + 1][row] = v.y;
            As[c4 * 4 + 2][row] = v.z; As[c4 * 4 + 3][row] = v.w;
        }
#pragma unroll
        for (int p = 0; p < 2; p++) {
            int idx = t * 2 + p;
            int row = idx >> 5, c4 = idx & 31;
            *reinterpret_cast<float4*>(&Bs[row][c4 * 4]) =
                *reinterpret_cast<const float4*>(Hsrc + (size_t)(k0 + row) * N_ + n0 + c4 * 4);
        }
        __syncthreads();
#pragma unroll
        for (int k = 0; k < 16; k++) {
            float a[4], bv[8];
            *reinterpret_cast<float4*>(&a[0])  = *reinterpret_cast<float4*>(&As[k][ty * 4]);
            *reinterpret_cast<float4*>(&bv[0]) = *reinterpret_cast<float4*>(&Bs[k][tx * 8]);
            *reinterpret_cast<float4*>(&bv[4]) = *reinterpret_cast<float4*>(&Bs[k][tx * 8 + 4]);
#pragma unroll
            for (int i = 0; i < 4; i++)
#pragma unroll
                for (int j = 0; j < 8; j++) acc[i][j] = fmaf(a[i], bv[j], acc[i][j]);
        }
        __syncthreads();
    }

    float* O = out + (size_t)b * Mrows * N_;
#pragma unroll
    for (int i = 0; i < 4; i++) {
        const float bval = bias[m0 + ty * 4 + i];
#pragma unroll
        for (int j = 0; j < 8; j++)
            O[(size_t)(m0 + ty * 4 + i) * N_ + n0 + tx * 8 + j] = acc[i][j] + bval;
    }
}

// ---------------- token MLP (tiny): warp-per-output dot products ----------------
__global__ void k_tok1(const float* __restrict__ t_in, const float* __restrict__ Wt1,
                       const float* __restrict__ bt1)
{
    const int b = blockIdx.x;
    const int w = threadIdx.x >> 5, lane = threadIdx.x & 31;
    const int m = blockIdx.y * 8 + w;
    const float* a = Wt1 + (size_t)m * C_;
    const float* v = t_in + (size_t)b * C_;
    float s = 0.f;
    for (int k = lane; k < C_; k += 32) s = fmaf(a[k], v[k], s);
#pragma unroll
    for (int o = 16; o; o >>= 1) s += __shfl_xor_sync(0xffffffffu, s, o);
    if (lane == 0) g_Ht[b * HID_ + m] = fmaxf(s + bt1[m], 0.f);
}

__global__ void k_tok2(const float* __restrict__ Wt2, const float* __restrict__ bt2)
{
    const int b = blockIdx.x;
    const int w = threadIdx.x >> 5, lane = threadIdx.x & 31;
    const int m = blockIdx.y * 8 + w;
    const float* a = Wt2 + (size_t)m * HID_;
    const float* v = g_Ht + (size_t)b * HID_;
    float s = 0.f;
    for (int k = lane; k < HID_; k += 32) s = fmaf(a[k], v[k], s);
#pragma unroll
    for (int o = 16; o; o >>= 1) s += __shfl_xor_sync(0xffffffffu, s, o);
    if (lane == 0) g_tok[b * G_ + m] = s + bt2[m];
}

// ---------------- Sinkhorn OT (3 iters) + exp, in place on g_P ----------------
__global__ void k_sinkhorn(const float* __restrict__ dust)
{
    const int b = blockIdx.x;
    const int tid = threadIdx.x;           // 1024 threads
    const float alpha = *dust;
    const float nrm = -logf((float)(M_ + N_));
    __shared__ float u[M_ + 1];
    __shared__ float v[N_];
    float* S = g_P + (size_t)b * M_ * N_;
    v[tid] = 0.f;
    __syncthreads();
    const int warp = tid >> 5, lane = tid & 31;

    for (int it = 0; it < 3; it++) {
        // u update: logsumexp over n of Z0[r,n]+v[n], warp-per-row
        for (int r = warp; r <= M_; r += 32) {
            float mx = -3.4e38f;
            if (r < M_) { for (int n = lane; n < N_; n += 32) mx = fmaxf(mx, S[r * N_ + n] + v[n]); }
            else        { for (int n = lane; n < N_; n += 32) mx = fmaxf(mx, alpha + v[n]); }
#pragma unroll
            for (int o = 16; o; o >>= 1) mx = fmaxf(mx, __shfl_xor_sync(0xffffffffu, mx, o));
            float s = 0.f;
            if (r < M_) { for (int n = lane; n < N_; n += 32) s += expf(S[r * N_ + n] + v[n] - mx); }
            else        { for (int n = lane; n < N_; n += 32) s += expf(alpha + v[n] - mx); }
#pragma unroll
            for (int o = 16; o; o >>= 1) s += __shfl_xor_sync(0xffffffffu, s, o);
            if (lane == 0) {
                float lmu = (r < M_) ? nrm : (logf((float)N_) + nrm);
                u[r] = lmu - (mx + logf(s));
            }
        }
        __syncthreads();
        // v update: logsumexp over 65 rows, thread-per-column
        {
            const int n = tid;
            float mx = alpha + u[M_];
            for (int r = 0; r < M_; r++) mx = fmaxf(mx, S[r * N_ + n] + u[r]);
            float s = expf(alpha + u[M_] - mx);
            for (int r = 0; r < M_; r++) s += expf(S[r * N_ + n] + u[r] - mx);
            v[n] = nrm - (mx + logf(s));
        }
        __syncthreads();
    }
    // P = exp(Z0 + u + v - norm), drop dust row (rows 0..63 only)
    for (int idx = tid; idx < M_ * N_; idx += 1024) {
        int r = idx >> 10, n = idx & (N_ - 1);
        S[idx] = expf(S[idx] + u[r] + v[n] - nrm);
    }
}

// ---------------- per-pixel column norm of f + temperature T ----------------
__global__ void k_coln(const float* __restrict__ Wtp, const float* __restrict__ btp)
{
    const int pid = blockIdx.x * blockDim.x + threadIdx.x;  // 16384 = B*N
    const int b = pid >> 10, n = pid & 1023;
    const float* F = g_F + (size_t)b * L_ * N_ + n;
    float ss = 0.f, tp = 0.f;
    for (int l = 0; l < L_; l++) {
        float vv = F[(size_t)l * N_];
        ss = fmaf(vv, vv, ss);
        tp = fmaf(vv, Wtp[l], tp);
    }
    g_RN[pid] = 1.f / fmaxf(sqrtf(ss), 1e-12f);
    float xx = tp + *btp;
    g_T[pid] = log1pf(expf(-fabsf(xx))) + fmaxf(xx, 0.f);   // stable softplus
}

// ---------------- burst: fused gram GEMM + sigmoid + row-sum -> discount ----------------
// discount[b,i] = clip( (sum_j sigmoid(0.5*(Ti+Tj)*sim_ij + bb))^bp , 1e-3, 1e3 )
// sim_ij = dot_l(f_i,f_j) * rn_i * rn_j  (sim never materialized: 67 MB avoided)
__global__ __launch_bounds__(256) void k_burst(const float* __restrict__ bbp,
                                               const float* __restrict__ bpp)
{
    const int b = blockIdx.y;
    const int i0 = blockIdx.x * 64;
    const float burst_b = *bbp;
    const float burst_p = *bpp;
    __shared__ float Af[128][64];       // full K-strip of i-tile (persistent)
    __shared__ float Bt[16][64];        // K-chunk of j-tile
    __shared__ float rnj[64], Tj[64];
    __shared__ float rs[64 * 16];
    const float* F = g_F + (size_t)b * L_ * N_;
    const int t = threadIdx.x, tx = t & 15, ty = t >> 4;

#pragma unroll
    for (int p = 0; p < 8; p++) {
        int idx = t + p * 256;          // 2048 float4 units
        int row = idx >> 4, c4 = idx & 15;
        *reinterpret_cast<float4*>(&Af[row][c4 * 4]) =
            *reinterpret_cast<const float4*>(F + (size_t)row * N_ + i0 + c4 * 4);
    }
    float rni[4], Ti[4];
#pragma unroll
    for (int i = 0; i < 4; i++) {
        rni[i] = g_RN[b * N_ + i0 + ty * 4 + i];
        Ti[i]  = g_T [b * N_ + i0 + ty * 4 + i];
    }
    float rowp[4] = {0.f, 0.f, 0.f, 0.f};

    for (int j0 = 0; j0 < N_; j0 += 64) {
        __syncthreads();                // previous epilogue done with rnj/Tj
        if (t < 64) { rnj[t] = g_RN[b * N_ + j0 + t]; Tj[t] = g_T[b * N_ + j0 + t]; }
        float acc[4][4];
#pragma unroll
        for (int i = 0; i < 4; i++)
#pragma unroll
            for (int j = 0; j < 4; j++) acc[i][j] = 0.f;

        for (int k0 = 0; k0 < L_; k0 += 16) {
            __syncthreads();            // previous Bt fully consumed
            {
                int row = t >> 4, c4 = t & 15;
                *reinterpret_cast<float4*>(&Bt[row][c4 * 4]) =
                    *reinterpret_cast<const float4*>(F + (size_t)(k0 + row) * N_ + j0 + c4 * 4);
            }
            __syncthreads();
#pragma unroll
            for (int k = 0; k < 16; k++) {
                float a[4], bv[4];
                *reinterpret_cast<float4*>(a)  = *reinterpret_cast<float4*>(&Af[k0 + k][ty * 4]);
                *reinterpret_cast<float4*>(bv) = *reinterpret_cast<float4*>(&Bt[k][tx * 4]);
#pragma unroll
                for (int i = 0; i < 4; i++)
#pragma unroll
                    for (int j = 0; j < 4; j++) acc[i][j] = fmaf(a[i], bv[j], acc[i][j]);
            }
        }
#pragma unroll
        for (int i = 0; i < 4; i++)
#pragma unroll
            for (int j = 0; j < 4; j++) {
                float sim = acc[i][j] * rni[i] * rnj[tx * 4 + j];
                float ta  = 0.5f * (Ti[i] + Tj[tx * 4 + j]);
                float z   = fmaf(ta, sim, burst_b);
                rowp[i] += 1.f / (1.f + __expf(-z));
            }
    }
    __syncthreads();
#pragma unroll
    for (int i = 0; i < 4; i++) rs[(ty * 4 + i) * 16 + tx] = rowp[i];
    __syncthreads();
    if (t < 64) {
        float s = 0.f;
        for (int xx = 0; xx < 16; xx++) s += rs[t * 16 + xx];
        float d = powf(s, burst_p);
        g_D[b * N_ + i0 + t] = fminf(fmaxf(d, 1e-3f), 1e3f);
    }
}

// ---------------- agg[b,l,m] = sum_n f[b,l,n] * P_adj[b,m,n]  (split-K, deterministic) ----------------
__global__ __launch_bounds__(256) void k_agg(const float* __restrict__ lamp)
{
    const int b = blockIdx.y;
    const int part = blockIdx.x;        // 8 n-splits of 128
    const int nbase = part * 128;
    const float lam = 1.f / (1.f + expf(-(*lamp)));
    const float oml = 1.f - lam;
    __shared__ float Ft[128][33];
    __shared__ float Pt[64][33];
    const int t = threadIdx.x, tx = t & 15, ty = t >> 4;
    const float* F = g_F + (size_t)b * L_ * N_;
    const float* P = g_P + (size_t)b * M_ * N_;

    float acc[8][4];
#pragma unroll
    for (int i = 0; i < 8; i++)
#pragma unroll
        for (int j = 0; j < 4; j++) acc[i][j] = 0.f;

    for (int tl = 0; tl < 4; tl++) {
        const int n0 = nbase + tl * 32;
        __syncthreads();
#pragma unroll
        for (int p = 0; p < 16; p++) {
            int idx = t + p * 256; int row = idx >> 5, c = idx & 31;
            Ft[row][c] = F[(size_t)row * N_ + n0 + c];
        }
#pragma unroll
        for (int p = 0; p < 8; p++) {
            int idx = t + p * 256; int row = idx >> 5, c = idx & 31;
            float d = g_D[b * N_ + n0 + c];
            Pt[row][c] = P[(size_t)row * N_ + n0 + c] * (oml + lam / (d + 1e-6f));
        }
        __syncthreads();
#pragma unroll
        for (int n = 0; n < 32; n++) {
            float a[8], pv[4];
#pragma unroll
            for (int i = 0; i < 8; i++) a[i] = Ft[ty * 8 + i][n];
#pragma unroll
            for (int j = 0; j < 4; j++) pv[j] = Pt[tx * 4 + j][n];
#pragma unroll
            for (int i = 0; i < 8; i++)
#pragma unroll
                for (int j = 0; j < 4; j++) acc[i][j] = fmaf(a[i], pv[j], acc[i][j]);
        }
    }
    float* O = g_aggp + ((size_t)b * 8 + part) * L_ * M_;
#pragma unroll
    for (int i = 0; i < 8; i++)
#pragma unroll
        for (int j = 0; j < 4; j++)
            O[(ty * 8 + i) * M_ + tx * 4 + j] = acc[i][j];
}

// ---------------- final: reduce split-K, normalize agg cols, tok norm, concat, global norm ----------------
__global__ void k_final(float* __restrict__ out)
{
    const int b = blockIdx.x, t = threadIdx.x;  // 256 threads
    __shared__ float sAgg[L_ * M_];             // 32 KB
    __shared__ float cn[64], cr[64], red[256];
    __shared__ float sh_tn, sh_gn;

    for (int idx = t; idx < L_ * M_; idx += 256) {
        float s = 0.f;
#pragma unroll
        for (int p = 0; p < 8; p++) s += g_aggp[((size_t)b * 8 + p) * L_ * M_ + idx];
        sAgg[idx] = s;
    }
    __syncthreads();

    if (t < 64) {
        float ss = 0.f;
        for (int l = 0; l < L_; l++) { float vv = sAgg[l * M_ + t]; ss = fmaf(vv, vv, ss); }
        float nn2 = fmaxf(sqrtf(ss), 1e-12f);
        cn[t] = nn2;
        cr[t] = ss / (nn2 * nn2);               // contribution to global norm
    }
    float tv = g_tok[b * G_ + t];
    red[t] = tv * tv;
    __syncthreads();
    for (int o = 128; o; o >>= 1) { if (t < o) red[t] += red[t + o]; __syncthreads(); }
    float tokss = red[0];
    __syncthreads();
    red[t] = (t < 64) ? cr[t] : 0.f;
    __syncthreads();
    for (int o = 128; o; o >>= 1) { if (t < o) red[t] += red[t + o]; __syncthreads(); }
    if (t == 0) {
        float tn = fmaxf(sqrtf(tokss), 1e-12f);
        float gss = tokss / (tn * tn) + red[0];
        sh_tn = tn;
        sh_gn = fmaxf(sqrtf(gss), 1e-12f);
    }
    __syncthreads();

    const int ob = b * (G_ + L_ * M_);
    out[ob + t] = tv / (sh_tn * sh_gn);
    const float invg = 1.f / sh_gn;
    for (int idx = t; idx < L_ * M_; idx += 256) {
        int mcol = idx & (M_ - 1);
        out[ob + G_ + idx] = sAgg[idx] * invg / cn[mcol];
    }
}

// ---------------- launch ----------------
extern "C" void kernel_launch(void* const* d_in, const int* in_sizes, int n_in,
                              void* d_out, int out_size)
{
    const float* x    = (const float*)d_in[0];
    const float* tt   = (const float*)d_in[1];
    const float* Wt1  = (const float*)d_in[2];
    const float* bt1  = (const float*)d_in[3];
    const float* Wt2  = (const float*)d_in[4];
    const float* bt2  = (const float*)d_in[5];
    const float* Wc1  = (const float*)d_in[6];
    const float* bc1  = (const float*)d_in[7];
    const float* Wc2  = (const float*)d_in[8];
    const float* bc2  = (const float*)d_in[9];
    const float* Ws1  = (const float*)d_in[10];
    const float* bs1  = (const float*)d_in[11];
    const float* Ws2  = (const float*)d_in[12];
    const float* bs2  = (const float*)d_in[13];
    const float* Wtp  = (const float*)d_in[14];
    const float* btp  = (const float*)d_in[15];
    const float* dust = (const float*)d_in[16];
    const float* bb   = (const float*)d_in[17];
    const float* bp   = (const float*)d_in[18];
    const float* ld   = (const float*)d_in[19];
    float* out = (float*)d_out;

    k_hidden  <<<dim3(8, 8, 16), 256>>>(x, Wc1, bc1, Ws1, bs1);
    k_gemm2   <<<dim3(8, 2, 16), 256>>>(Wc2, bc2, 0, 0);     // f
    k_gemm2   <<<dim3(8, 1, 16), 256>>>(Ws2, bs2, 512, 1);   // p
    k_tok1    <<<dim3(16, 64), 256>>>(tt, Wt1, bt1);
    k_tok2    <<<dim3(16, 32), 256>>>(Wt2, bt2);
    k_sinkhorn<<<16, 1024>>>(dust);
    k_coln    <<<64, 256>>>(Wtp, btp);
    k_burst   <<<dim3(16, 16), 256>>>(bb, bp);
    k_agg     <<<dim3(8, 16), 256>>>(ld);
    k_final   <<<16, 256>>>(out);
}

// round 2
// speedup vs baseline: 1.7390x; 1.7390x over previous
#include <cuda_runtime.h>
#include <cuda_bf16.h>
#include <math.h>
#include <stdint.h>

#define B_   16
#define C_   1536
#define N_   1024
#define M_   64
#define L_   128
#define G_   256
#define HID_ 512

// ---------------- scratch (device globals: no allocation allowed) ----------------
static __device__ float g_H   [B_ * 1024 * N_];   // 64 MB fp32 hidden (h1 rows 0..511, h2 rows 512..1023)
static __device__ __nv_bfloat16 g_Xh[B_ * C_ * N_];
static __device__ __nv_bfloat16 g_Xl[B_ * C_ * N_];
static __device__ __nv_bfloat16 g_Wh[1024 * C_];  // rows 0..511 = Wc1, 512..1023 = Ws1
static __device__ __nv_bfloat16 g_Wl[1024 * C_];
static __device__ float g_F   [B_ * L_ * N_];     // f
static __device__ float g_P   [B_ * M_ * N_];     // scores p -> transport P (in place)
static __device__ float g_T   [B_ * N_];          // T_i
static __device__ float g_RN  [B_ * N_];          // 1/max(||f_col||,1e-12)
static __device__ float g_D   [B_ * N_];          // discount
static __device__ float g_Ht  [B_ * HID_];
static __device__ float g_tok [B_ * G_];
static __device__ float g_aggp[B_ * 8 * L_ * M_]; // split-K partials (deterministic)

// ---------------- PTX helpers ----------------
__device__ __forceinline__ void ldm_x4(uint32_t &r0, uint32_t &r1, uint32_t &r2, uint32_t &r3, uint32_t addr) {
    asm volatile("ldmatrix.sync.aligned.m8n8.x4.shared.b16 {%0,%1,%2,%3}, [%4];"
                 : "=r"(r0), "=r"(r1), "=r"(r2), "=r"(r3) : "r"(addr));
}
__device__ __forceinline__ void ldm_x2t(uint32_t &r0, uint32_t &r1, uint32_t addr) {
    asm volatile("ldmatrix.sync.aligned.m8n8.x2.trans.shared.b16 {%0,%1}, [%2];"
                 : "=r"(r0), "=r"(r1) : "r"(addr));
}
__device__ __forceinline__ void mma16816(float* c, const uint32_t* a, const uint32_t* b) {
    asm volatile("mma.sync.aligned.m16n8k16.row.col.f32.bf16.bf16.f32 "
                 "{%0,%1,%2,%3},{%4,%5,%6,%7},{%8,%9},{%0,%1,%2,%3};"
                 : "+f"(c[0]), "+f"(c[1]), "+f"(c[2]), "+f"(c[3])
                 : "r"(a[0]), "r"(a[1]), "r"(a[2]), "r"(a[3]), "r"(b[0]), "r"(b[1]));
}
__device__ __forceinline__ void cp16(uint32_t saddr, const void* gaddr) {
    asm volatile("cp.async.cg.shared.global [%0], [%1], 16;" :: "r"(saddr), "l"(gaddr));
}
#define CP_COMMIT() asm volatile("cp.async.commit_group;")
#define CP_WAIT(n)  asm volatile("cp.async.wait_group %0;" :: "n"(n))

// ---------------- split fp32 -> bf16 hi/lo pairs ----------------
__global__ void k_split(const float* __restrict__ src, int n4, int which, size_t off)
{
    __nv_bfloat16* Hi = which ? g_Wh : g_Xh;
    __nv_bfloat16* Lo = which ? g_Wl : g_Xl;
    for (int i = blockIdx.x * blockDim.x + threadIdx.x; i < n4; i += gridDim.x * blockDim.x) {
        float4 v = reinterpret_cast<const float4*>(src)[i];
        __nv_bfloat16 h0 = __float2bfloat16_rn(v.x);
        __nv_bfloat16 h1 = __float2bfloat16_rn(v.y);
        __nv_bfloat16 h2 = __float2bfloat16_rn(v.z);
        __nv_bfloat16 h3 = __float2bfloat16_rn(v.w);
        __nv_bfloat16 l0 = __float2bfloat16_rn(v.x - __bfloat162float(h0));
        __nv_bfloat16 l1 = __float2bfloat16_rn(v.y - __bfloat162float(h1));
        __nv_bfloat16 l2 = __float2bfloat16_rn(v.z - __bfloat162float(h2));
        __nv_bfloat16 l3 = __float2bfloat16_rn(v.w - __bfloat162float(h3));
        __nv_bfloat162 ph0 = {h0, h1}, ph1 = {h2, h3}, pl0 = {l0, l1}, pl1 = {l2, l3};
        uint2 uh = {*reinterpret_cast<uint32_t*>(&ph0), *reinterpret_cast<uint32_t*>(&ph1)};
        uint2 ul = {*reinterpret_cast<uint32_t*>(&pl0), *reinterpret_cast<uint32_t*>(&pl1)};
        *reinterpret_cast<uint2*>(Hi + off + (size_t)i * 4) = uh;
        *reinterpret_cast<uint2*>(Lo + off + (size_t)i * 4) = ul;
    }
}

// ---------------- big GEMM on tensor cores: h = relu(W*x + b), bf16 3-split ----------------
// C[b,m,n] = sum_k W[m,k]*X[b,k,n]; tile 128(M)x128(N), K-chunks of 16, double-buffered cp.async
__global__ __launch_bounds__(256, 1) void k_hidden_mma(
    const float* __restrict__ bc1, const float* __restrict__ bs1)
{
    const int b  = blockIdx.z;
    const int m0 = blockIdx.y * 128;
    const int n0 = blockIdx.x * 128;

    __shared__ __align__(16) __nv_bfloat16 sAh[2][2048];  // [buf][m(128) x k(16)] swizzled
    __shared__ __align__(16) __nv_bfloat16 sAl[2][2048];
    __shared__ __align__(16) __nv_bfloat16 sBh[2][2048];  // [buf][k(16) x n(128)] swizzled
    __shared__ __align__(16) __nv_bfloat16 sBl[2][2048];

    const int t = threadIdx.x;
    const int w = t >> 5, lane = t & 31;
    const int wm = (w >> 2) * 64;          // warp m offset (2 rows of warps)
    const int wn = (w & 3) * 32;           // warp n offset (4 cols of warps)
    const int g = lane >> 2, tg = lane & 3;

    const __nv_bfloat16* gWh = g_Wh + (size_t)m0 * C_;
    const __nv_bfloat16* gWl = g_Wl + (size_t)m0 * C_;
    const __nv_bfloat16* gXh = g_Xh + (size_t)b * C_ * N_;
    const __nv_bfloat16* gXl = g_Xl + (size_t)b * C_ * N_;

    const uint32_t bAh = (uint32_t)__cvta_generic_to_shared(&sAh[0][0]);
    const uint32_t bAl = (uint32_t)__cvta_generic_to_shared(&sAl[0][0]);
    const uint32_t bBh = (uint32_t)__cvta_generic_to_shared(&sBh[0][0]);
    const uint32_t bBl = (uint32_t)__cvta_generic_to_shared(&sBl[0][0]);

    // per-thread copy coordinates (16B units)
    const int am = t >> 1, ac = t & 1;                       // A: 128 m x 2 chunks
    const uint32_t aso = 16u * (uint32_t)(am * 2 + (ac ^ ((am >> 2) & 1)));
    const size_t   ago = (size_t)am * C_ + ac * 8;
    const int bk = t >> 4, bc = t & 15;                      // B: 16 k x 16 chunks
    const uint32_t bso = 16u * (uint32_t)(bk * 16 + (bc ^ (bk & 7)));
    const size_t   bgo = (size_t)bk * N_ + n0 + bc * 8;

    float acc[4][4][4];
#pragma unroll
    for (int i = 0; i < 4; i++)
#pragma unroll
        for (int j = 0; j < 4; j++)
#pragma unroll
            for (int q = 0; q < 4; q++) acc[i][j][q] = 0.f;

    // ldmatrix address offsets (constant per thread across iterations)
    uint32_t aoff[4], boff[4];
    {
        const int arow = lane & 15, ak = lane >> 4;
#pragma unroll
        for (int mt = 0; mt < 4; mt++) {
            int r = wm + mt * 16 + arow;
            aoff[mt] = 16u * (uint32_t)(r * 2 + (ak ^ ((r >> 2) & 1)));
        }
        const int bk2 = lane & 15;
#pragma unroll
        for (int nt = 0; nt < 4; nt++) {
            int cn = (w & 3) * 4 + nt;
            boff[nt] = 16u * (uint32_t)(bk2 * 16 + (cn ^ (bk2 & 7)));
        }
    }

    // prologue: stage 0
    {
        cp16(bAh + aso, gWh + ago);
        cp16(bAl + aso, gWl + ago);
        cp16(bBh + bso, gXh + bgo);
        cp16(bBl + bso, gXl + bgo);
        CP_COMMIT();
    }

    const int NIT = C_ / 16;   // 96
    for (int it = 0; it < NIT; it++) {
        if (it + 1 < NIT) {
            const int k0 = (it + 1) * 16;
            const uint32_t bufo = ((it + 1) & 1) * 4096u;
            cp16(bAh + bufo + aso, gWh + (size_t)k0 + ago);
            cp16(bAl + bufo + aso, gWl + (size_t)k0 + ago);
            cp16(bBh + bufo + bso, gXh + (size_t)k0 * N_ + bgo);
            cp16(bBl + bufo + bso, gXl + (size_t)k0 * N_ + bgo);
            CP_COMMIT();
            CP_WAIT(1);
        } else {
            CP_WAIT(0);
        }
        __syncthreads();

        const uint32_t bufo = (it & 1) * 4096u;
        uint32_t ah[4][4], al[4][4], bh[4][2], bl[4][2];
#pragma unroll
        for (int mt = 0; mt < 4; mt++) {
            ldm_x4(ah[mt][0], ah[mt][1], ah[mt][2], ah[mt][3], bAh + bufo + aoff[mt]);
            ldm_x4(al[mt][0], al[mt][1], al[mt][2], al[mt][3], bAl + bufo + aoff[mt]);
        }
#pragma unroll
        for (int nt = 0; nt < 4; nt++) {
            ldm_x2t(bh[nt][0], bh[nt][1], bBh + bufo + boff[nt]);
            ldm_x2t(bl[nt][0], bl[nt][1], bBl + bufo + boff[nt]);
        }
#pragma unroll
        for (int mt = 0; mt < 4; mt++)
#pragma unroll
            for (int nt = 0; nt < 4; nt++) {
                mma16816(acc[mt][nt], ah[mt], bh[nt]);
                mma16816(acc[mt][nt], ah[mt], bl[nt]);
                mma16816(acc[mt][nt], al[mt], bh[nt]);
            }
        __syncthreads();
    }

    // epilogue: + bias, relu, fp32 store
    const float* bptr = (m0 >= HID_) ? (bs1 - HID_) : bc1;
    float* O = g_H + (size_t)b * 1024 * N_;
#pragma unroll
    for (int mt = 0; mt < 4; mt++) {
        const int m = m0 + wm + mt * 16 + g;
        const float bv0 = bptr[m];
        const float bv1 = bptr[m + 8];
#pragma unroll
        for (int nt = 0; nt < 4; nt++) {
            const int n = n0 + wn + nt * 8 + 2 * tg;
            float2 v0 = {fmaxf(acc[mt][nt][0] + bv0, 0.f), fmaxf(acc[mt][nt][1] + bv0, 0.f)};
            float2 v1 = {fmaxf(acc[mt][nt][2] + bv1, 0.f), fmaxf(acc[mt][nt][3] + bv1, 0.f)};
            *reinterpret_cast<float2*>(O + (size_t)m * N_ + n)       = v0;
            *reinterpret_cast<float2*>(O + (size_t)(m + 8) * N_ + n) = v1;
        }
    }
}

// ---------------- second-layer GEMMs: f (flag=0) / p (flag=1), K=512 ----------------
__global__ __launch_bounds__(256) void k_gemm2(
    const float* __restrict__ A, const float* __restrict__ bias, int koff, int flag)
{
    const int b  = blockIdx.z;
    const int m0 = blockIdx.y * 64;
    const int n0 = blockIdx.x * 128;
    float* out = flag ? g_P : g_F;
    const int Mrows = flag ? M_ : L_;
    const float* Hsrc = g_H + (size_t)b * 1024 * N_ + (size_t)koff * N_;

    __shared__ float As[16][64];
    __shared__ float Bs[16][128];
    const int t = threadIdx.x, tx = t & 15, ty = t >> 4;

    float acc[4][8];
#pragma unroll
    for (int i = 0; i < 4; i++)
#pragma unroll
        for (int j = 0; j < 8; j++) acc[i][j] = 0.f;

    for (int k0 = 0; k0 < HID_; k0 += 16) {
        {
            int row = t >> 2, c4 = t & 3;
            float4 v = *reinterpret_cast<const float4*>(A + (size_t)(m0 + row) * HID_ + k0 + c4 * 4);
            As[c4 * 4 + 0][row] = v.x; As[c4 * 4 + 1][row] = v.y;
            As[c4 * 4 + 2][row] = v.z; As[c4 * 4 + 3][row] = v.w;
        }
#pragma unroll
        for (int p = 0; p < 2; p++) {
            int idx = t * 2 + p;
            int row = idx >> 5, c4 = idx & 31;
            *reinterpret_cast<float4*>(&Bs[row][c4 * 4]) =
                *reinterpret_cast<const float4*>(Hsrc + (size_t)(k0 + row) * N_ + n0 + c4 * 4);
        }
        __syncthreads();
#pragma unroll
        for (int k = 0; k < 16; k++) {
            float a[4], bv[8];
            *reinterpret_cast<float4*>(&a[0])  = *reinterpret_cast<float4*>(&As[k][ty * 4]);
            *reinterpret_cast<float4*>(&bv[0]) = *reinterpret_cast<float4*>(&Bs[k][tx * 8]);
            *reinterpret_cast<float4*>(&bv[4]) = *reinterpret_cast<float4*>(&Bs[k][tx * 8 + 4]);
#pragma unroll
            for (int i = 0; i < 4; i++)
#pragma unroll
                for (int j = 0; j < 8; j++) acc[i][j] = fmaf(a[i], bv[j], acc[i][j]);
        }
        __syncthreads();
    }

    float* O = out + (size_t)b * Mrows * N_;
#pragma unroll
    for (int i = 0; i < 4; i++) {
        const float bval = bias[m0 + ty * 4 + i];
#pragma unroll
        for (int j = 0; j < 8; j++)
            O[(size_t)(m0 + ty * 4 + i) * N_ + n0 + tx * 8 + j] = acc[i][j] + bval;
    }
}

// ---------------- token MLP ----------------
__global__ void k_tok1(const float* __restrict__ t_in, const float* __restrict__ Wt1,
                       const float* __restrict__ bt1)
{
    const int b = blockIdx.x;
    const int w = threadIdx.x >> 5, lane = threadIdx.x & 31;
    const int m = blockIdx.y * 8 + w;
    const float* a = Wt1 + (size_t)m * C_;
    const float* v = t_in + (size_t)b * C_;
    float s = 0.f;
    for (int k = lane; k < C_; k += 32) s = fmaf(a[k], v[k], s);
#pragma unroll
    for (int o = 16; o; o >>= 1) s += __shfl_xor_sync(0xffffffffu, s, o);
    if (lane == 0) g_Ht[b * HID_ + m] = fmaxf(s + bt1[m], 0.f);
}

__global__ void k_tok2(const float* __restrict__ Wt2, const float* __restrict__ bt2)
{
    const int b = blockIdx.x;
    const int w = threadIdx.x >> 5, lane = threadIdx.x & 31;
    const int m = blockIdx.y * 8 + w;
    const float* a = Wt2 + (size_t)m * HID_;
    const float* v = g_Ht + (size_t)b * HID_;
    float s = 0.f;
    for (int k = lane; k < HID_; k += 32) s = fmaf(a[k], v[k], s);
#pragma unroll
    for (int o = 16; o; o >>= 1) s += __shfl_xor_sync(0xffffffffu, s, o);
    if (lane == 0) g_tok[b * G_ + m] = s + bt2[m];
}

// ---------------- Sinkhorn OT (3 iters) + exp, in place on g_P ----------------
__global__ void k_sinkhorn(const float* __restrict__ dust)
{
    const int b = blockIdx.x;
    const int tid = threadIdx.x;           // 1024 threads
    const float alpha = *dust;
    const float nrm = -logf((float)(M_ + N_));
    __shared__ float u[M_ + 1];
    __shared__ float v[N_];
    float* S = g_P + (size_t)b * M_ * N_;
    v[tid] = 0.f;
    __syncthreads();
    const int warp = tid >> 5, lane = tid & 31;

    for (int it = 0; it < 3; it++) {
        for (int r = warp; r <= M_; r += 32) {
            float mx = -3.4e38f;
            if (r < M_) { for (int n = lane; n < N_; n += 32) mx = fmaxf(mx, S[r * N_ + n] + v[n]); }
            else        { for (int n = lane; n < N_; n += 32) mx = fmaxf(mx, alpha + v[n]); }
#pragma unroll
            for (int o = 16; o; o >>= 1) mx = fmaxf(mx, __shfl_xor_sync(0xffffffffu, mx, o));
            float s = 0.f;
            if (r < M_) { for (int n = lane; n < N_; n += 32) s += expf(S[r * N_ + n] + v[n] - mx); }
            else        { for (int n = lane; n < N_; n += 32) s += expf(alpha + v[n] - mx); }
#pragma unroll
            for (int o = 16; o; o >>= 1) s += __shfl_xor_sync(0xffffffffu, s, o);
            if (lane == 0) {
                float lmu = (r < M_) ? nrm : (logf((float)N_) + nrm);
                u[r] = lmu - (mx + logf(s));
            }
        }
        __syncthreads();
        {
            const int n = tid;
            float mx = alpha + u[M_];
            for (int r = 0; r < M_; r++) mx = fmaxf(mx, S[r * N_ + n] + u[r]);
            float s = expf(alpha + u[M_] - mx);
            for (int r = 0; r < M_; r++) s += expf(S[r * N_ + n] + u[r] - mx);
            v[n] = nrm - (mx + logf(s));
        }
        __syncthreads();
    }
    for (int idx = tid; idx < M_ * N_; idx += 1024) {
        int r = idx >> 10, n = idx & (N_ - 1);
        S[idx] = expf(S[idx] + u[r] + v[n] - nrm);
    }
}

// ---------------- per-pixel column norm of f + temperature T ----------------
__global__ void k_coln(const float* __restrict__ Wtp, const float* __restrict__ btp)
{
    const int pid = blockIdx.x * blockDim.x + threadIdx.x;  // 16384 = B*N
    const int b = pid >> 10, n = pid & 1023;
    const float* F = g_F + (size_t)b * L_ * N_ + n;
    float ss = 0.f, tp = 0.f;
    for (int l = 0; l < L_; l++) {
        float vv = F[(size_t)l * N_];
        ss = fmaf(vv, vv, ss);
        tp = fmaf(vv, Wtp[l], tp);
    }
    g_RN[pid] = 1.f / fmaxf(sqrtf(ss), 1e-12f);
    float xx = tp + *btp;
    g_T[pid] = log1pf(expf(-fabsf(xx))) + fmaxf(xx, 0.f);
}

// ---------------- burst: fused gram GEMM + sigmoid + row-sum -> discount ----------------
__global__ __launch_bounds__(256) void k_burst(const float* __restrict__ bbp,
                                               const float* __restrict__ bpp)
{
    const int b = blockIdx.y;
    const int i0 = blockIdx.x * 64;
    const float burst_b = *bbp;
    const float burst_p = *bpp;
    __shared__ float Af[128][64];
    __shared__ float Bt[16][64];
    __shared__ float rnj[64], Tj[64];
    __shared__ float rs[64 * 16];
    const float* F = g_F + (size_t)b * L_ * N_;
    const int t = threadIdx.x, tx = t & 15, ty = t >> 4;

#pragma unroll
    for (int p = 0; p < 8; p++) {
        int idx = t + p * 256;
        int row = idx >> 4, c4 = idx & 15;
        *reinterpret_cast<float4*>(&Af[row][c4 * 4]) =
            *reinterpret_cast<const float4*>(F + (size_t)row * N_ + i0 + c4 * 4);
    }
    float rni[4], Ti[4];
#pragma unroll
    for (int i = 0; i < 4; i++) {
        rni[i] = g_RN[b * N_ + i0 + ty * 4 + i];
        Ti[i]  = g_T [b * N_ + i0 + ty * 4 + i];
    }
    float rowp[4] = {0.f, 0.f, 0.f, 0.f};

    for (int j0 = 0; j0 < N_; j0 += 64) {
        __syncthreads();
        if (t < 64) { rnj[t] = g_RN[b * N_ + j0 + t]; Tj[t] = g_T[b * N_ + j0 + t]; }
        float acc[4][4];
#pragma unroll
        for (int i = 0; i < 4; i++)
#pragma unroll
            for (int j = 0; j < 4; j++) acc[i][j] = 0.f;

        for (int k0 = 0; k0 < L_; k0 += 16) {
            __syncthreads();
            {
                int row = t >> 4, c4 = t & 15;
                *reinterpret_cast<float4*>(&Bt[row][c4 * 4]) =
                    *reinterpret_cast<const float4*>(F + (size_t)(k0 + row) * N_ + j0 + c4 * 4);
            }
            __syncthreads();
#pragma unroll
            for (int k = 0; k < 16; k++) {
                float a[4], bv[4];
                *reinterpret_cast<float4*>(a)  = *reinterpret_cast<float4*>(&Af[k0 + k][ty * 4]);
                *reinterpret_cast<float4*>(bv) = *reinterpret_cast<float4*>(&Bt[k][tx * 4]);
#pragma unroll
                for (int i = 0; i < 4; i++)
#pragma unroll
                    for (int j = 0; j < 4; j++) acc[i][j] = fmaf(a[i], bv[j], acc[i][j]);
            }
        }
#pragma unroll
        for (int i = 0; i < 4; i++)
#pragma unroll
            for (int j = 0; j < 4; j++) {
                float sim = acc[i][j] * rni[i] * rnj[tx * 4 + j];
                float ta  = 0.5f * (Ti[i] + Tj[tx * 4 + j]);
                float z   = fmaf(ta, sim, burst_b);
                rowp[i] += 1.f / (1.f + __expf(-z));
            }
    }
    __syncthreads();
#pragma unroll
    for (int i = 0; i < 4; i++) rs[(ty * 4 + i) * 16 + tx] = rowp[i];
    __syncthreads();
    if (t < 64) {
        float s = 0.f;
        for (int xx = 0; xx < 16; xx++) s += rs[t * 16 + xx];
        float d = powf(s, burst_p);
        g_D[b * N_ + i0 + t] = fminf(fmaxf(d, 1e-3f), 1e3f);
    }
}

// ---------------- agg[b,l,m] = sum_n f[b,l,n] * P_adj[b,m,n]  (split-K, deterministic) ----------------
__global__ __launch_bounds__(256) void k_agg(const float* __restrict__ lamp)
{
    const int b = blockIdx.y;
    const int part = blockIdx.x;
    const int nbase = part * 128;
    const float lam = 1.f / (1.f + expf(-(*lamp)));
    const float oml = 1.f - lam;
    __shared__ float Ft[128][33];
    __shared__ float Pt[64][33];
    const int t = threadIdx.x, tx = t & 15, ty = t >> 4;
    const float* F = g_F + (size_t)b * L_ * N_;
    const float* P = g_P + (size_t)b * M_ * N_;

    float acc[8][4];
#pragma unroll
    for (int i = 0; i < 8; i++)
#pragma unroll
        for (int j = 0; j < 4; j++) acc[i][j] = 0.f;

    for (int tl = 0; tl < 4; tl++) {
        const int n0 = nbase + tl * 32;
        __syncthreads();
#pragma unroll
        for (int p = 0; p < 16; p++) {
            int idx = t + p * 256; int row = idx >> 5, c = idx & 31;
            Ft[row][c] = F[(size_t)row * N_ + n0 + c];
        }
#pragma unroll
        for (int p = 0; p < 8; p++) {
            int idx = t + p * 256; int row = idx >> 5, c = idx & 31;
            float d = g_D[b * N_ + n0 + c];
            Pt[row][c] = P[(size_t)row * N_ + n0 + c] * (oml + lam / (d + 1e-6f));
        }
        __syncthreads();
#pragma unroll
        for (int n = 0; n < 32; n++) {
            float a[8], pv[4];
#pragma unroll
            for (int i = 0; i < 8; i++) a[i] = Ft[ty * 8 + i][n];
#pragma unroll
            for (int j = 0; j < 4; j++) pv[j] = Pt[tx * 4 + j][n];
#pragma unroll
            for (int i = 0; i < 8; i++)
#pragma unroll
                for (int j = 0; j < 4; j++) acc[i][j] = fmaf(a[i], pv[j], acc[i][j]);
        }
    }
    float* O = g_aggp + ((size_t)b * 8 + part) * L_ * M_;
#pragma unroll
    for (int i = 0; i < 8; i++)
#pragma unroll
        for (int j = 0; j < 4; j++)
            O[(ty * 8 + i) * M_ + tx * 4 + j] = acc[i][j];
}

// ---------------- final reduce + normalize + concat ----------------
__global__ void k_final(float* __restrict__ out)
{
    const int b = blockIdx.x, t = threadIdx.x;
    __shared__ float sAgg[L_ * M_];
    __shared__ float cn[64], cr[64], red[256];
    __shared__ float sh_tn, sh_gn;

    for (int idx = t; idx < L_ * M_; idx += 256) {
        float s = 0.f;
#pragma unroll
        for (int p = 0; p < 8; p++) s += g_aggp[((size_t)b * 8 + p) * L_ * M_ + idx];
        sAgg[idx] = s;
    }
    __syncthreads();

    if (t < 64) {
        float ss = 0.f;
        for (int l = 0; l < L_; l++) { float vv = sAgg[l * M_ + t]; ss = fmaf(vv, vv, ss); }
        float nn2 = fmaxf(sqrtf(ss), 1e-12f);
        cn[t] = nn2;
        cr[t] = ss / (nn2 * nn2);
    }
    float tv = g_tok[b * G_ + t];
    red[t] = tv * tv;
    __syncthreads();
    for (int o = 128; o; o >>= 1) { if (t < o) red[t] += red[t + o]; __syncthreads(); }
    float tokss = red[0];
    __syncthreads();
    red[t] = (t < 64) ? cr[t] : 0.f;
    __syncthreads();
    for (int o = 128; o; o >>= 1) { if (t < o) red[t] += red[t + o]; __syncthreads(); }
    if (t == 0) {
        float tn = fmaxf(sqrtf(tokss), 1e-12f);
        float gss = tokss / (tn * tn) + red[0];
        sh_tn = tn;
        sh_gn = fmaxf(sqrtf(gss), 1e-12f);
    }
    __syncthreads();

    const int ob = b * (G_ + L_ * M_);
    out[ob + t] = tv / (sh_tn * sh_gn);
    const float invg = 1.f / sh_gn;
    for (int idx = t; idx < L_ * M_; idx += 256) {
        int mcol = idx & (M_ - 1);
        out[ob + G_ + idx] = sAgg[idx] * invg / cn[mcol];
    }
}

// ---------------- launch ----------------
extern "C" void kernel_launch(void* const* d_in, const int* in_sizes, int n_in,
                              void* d_out, int out_size)
{
    const float* x    = (const float*)d_in[0];
    const float* tt   = (const float*)d_in[1];
    const float* Wt1  = (const float*)d_in[2];
    const float* bt1  = (const float*)d_in[3];
    const float* Wt2  = (const float*)d_in[4];
    const float* bt2  = (const float*)d_in[5];
    const float* Wc1  = (const float*)d_in[6];
    const float* bc1  = (const float*)d_in[7];
    const float* Wc2  = (const float*)d_in[8];
    const float* bc2  = (const float*)d_in[9];
    const float* Ws1  = (const float*)d_in[10];
    const float* bs1  = (const float*)d_in[11];
    const float* Ws2  = (const float*)d_in[12];
    const float* bs2  = (const float*)d_in[13];
    const float* Wtp  = (const float*)d_in[14];
    const float* btp  = (const float*)d_in[15];
    const float* dust = (const float*)d_in[16];
    const float* bb   = (const float*)d_in[17];
    const float* bp   = (const float*)d_in[18];
    const float* ld   = (const float*)d_in[19];
    float* out = (float*)d_out;

    // bf16 hi/lo splits
    k_split<<<1024, 256>>>(x,   (B_ * C_ * N_) / 4, 0, 0);
    k_split<<<64,  256>>>(Wc1, (HID_ * C_) / 4,    1, 0);
    k_split<<<64,  256>>>(Ws1, (HID_ * C_) / 4,    1, (size_t)HID_ * C_);

    k_hidden_mma<<<dim3(8, 8, 16), 256>>>(bc1, bs1);
    k_gemm2   <<<dim3(8, 2, 16), 256>>>(Wc2, bc2, 0, 0);     // f
    k_gemm2   <<<dim3(8, 1, 16), 256>>>(Ws2, bs2, 512, 1);   // p
    k_tok1    <<<dim3(16, 64), 256>>>(tt, Wt1, bt1);
    k_tok2    <<<dim3(16, 32), 256>>>(Wt2, bt2);
    k_sinkhorn<<<16, 1024>>>(dust);
    k_coln    <<<64, 256>>>(Wtp, btp);
    k_burst   <<<dim3(16, 16), 256>>>(bb, bp);
    k_agg     <<<dim3(8, 16), 256>>>(ld);
    k_final   <<<16, 256>>>(out);
}